// round 9
// baseline (speedup 1.0000x reference)
#include <cuda_runtime.h>
#include <cuda_bf16.h>
#include <mma.h>
#include <cstdint>

using namespace nvcuda;

#define N_MAX 100000
#define E_MAX 1000000
#define NB_MAX 128            // ceil(N_MAX/1024) = 98
#define NPAD (N_MAX + 128)    // feature rows padded so edge-tile wmma loads stay in-bounds

// ---------------- device scratch (static; device-side references only) ----------------
__device__ int g_cnt[N_MAX];
__device__ int g_rowptr[N_MAX + 1];
__device__ int g_cursor[N_MAX];
__device__ int g_csr[E_MAX];
__device__ int g_bsum[NB_MAX];
__device__ __nv_bfloat16 g_xh[(size_t)NPAD * 64];
__device__ __nv_bfloat16 g_xl[(size_t)NPAD * 64];
__device__ __nv_bfloat16 g_hh[(size_t)NPAD * 64];
__device__ __nv_bfloat16 g_hl[(size_t)NPAD * 64];
__device__ float g_yl[(size_t)N_MAX * 64];   // lin_l projection (gathered by agg)
__device__ float g_yr[(size_t)N_MAX * 64];   // lin_r projection (root)
// W' = [W_l;W_r] TRANSPOSED: [64 k][128 n] row-major, bf16 hi/lo
__device__ __align__(16) __nv_bfloat16 g_wth[2][8192];
__device__ __align__(16) __nv_bfloat16 g_wtl[2][8192];

// ---------------- CSR build ----------------
__global__ void zero_k(int n) {
    int i = blockIdx.x * blockDim.x + threadIdx.x;
    if (i < n) g_cnt[i] = 0;
}

__global__ void count_k(const int* __restrict__ dst, int e, int n) {
    int i = blockIdx.x * blockDim.x + threadIdx.x;
    if (i < e) {
        int d = dst[i];
        if ((unsigned)d < (unsigned)n) atomicAdd(&g_cnt[d], 1);
    }
}

__global__ void scan1_k(int n) {
    int base = blockIdx.x * 1024;
    int t = threadIdx.x;
    int i0 = base + t * 4;
    int s = 0;
#pragma unroll
    for (int j = 0; j < 4; j++) {
        int i = i0 + j;
        if (i < n) s += g_cnt[i];
    }
#pragma unroll
    for (int o = 16; o; o >>= 1) s += __shfl_down_sync(0xffffffffu, s, o);
    __shared__ int ws[8];
    if ((t & 31) == 0) ws[t >> 5] = s;
    __syncthreads();
    if (t == 0) {
        int tot = 0;
#pragma unroll
        for (int j = 0; j < 8; j++) tot += ws[j];
        g_bsum[blockIdx.x] = tot;
    }
}

// merged scan2+scan3: each block derives its exclusive base from g_bsum itself
__global__ void scan23_k(int n, int e) {
    int t = threadIdx.x;
    int bid = blockIdx.x;
    int val = (t < bid) ? g_bsum[t] : 0;   // bid <= 97 < 256
#pragma unroll
    for (int o = 16; o; o >>= 1) val += __shfl_down_sync(0xffffffffu, val, o);
    __shared__ int wsb[8];
    __shared__ int s_base;
    if ((t & 31) == 0) wsb[t >> 5] = val;
    __syncthreads();
    if (t == 0) {
        int b = 0;
#pragma unroll
        for (int j = 0; j < 8; j++) b += wsb[j];
        s_base = b;
        if (bid == 0) g_rowptr[n] = e;
    }
    __syncthreads();
    int base = s_base;

    int lane = t & 31, wid = t >> 5;
    int i0 = bid * 1024 + t * 4;
    int v[4];
    int tsum = 0;
#pragma unroll
    for (int j = 0; j < 4; j++) {
        v[j] = (i0 + j < n) ? g_cnt[i0 + j] : 0;
        tsum += v[j];
    }
    int incl = tsum;
#pragma unroll
    for (int o = 1; o < 32; o <<= 1) {
        int u = __shfl_up_sync(0xffffffffu, incl, o);
        if (lane >= o) incl += u;
    }
    __shared__ int ws[8];
    if (lane == 31) ws[wid] = incl;
    __syncthreads();
    if (t < 8) {
        int u = ws[t];
        int inc = u;
#pragma unroll
        for (int o = 1; o < 8; o <<= 1) {
            int q = __shfl_up_sync(0xffu, inc, o);
            if (t >= o) inc += q;
        }
        ws[t] = inc - u;
    }
    __syncthreads();
    int excl = incl - tsum + ws[wid] + base;
#pragma unroll
    for (int j = 0; j < 4; j++) {
        int i = i0 + j;
        if (i < n) {
            g_rowptr[i] = excl;
            g_cursor[i] = excl;
            excl += v[j];
        }
    }
}

__global__ void fill_k(const int* __restrict__ src, const int* __restrict__ dst, int e, int n) {
    int i = blockIdx.x * blockDim.x + threadIdx.x;
    if (i < e) {
        int d = dst[i];
        int s = src[i];
        if ((unsigned)d < (unsigned)n && (unsigned)s < (unsigned)n) {
            int pos = atomicAdd(&g_cursor[d], 1);
            g_csr[pos] = s;
        }
    }
}

// ---------------- x -> bf16 hi/lo split ----------------
__global__ void conv_k(const float* __restrict__ x, int npairs) {
    int i = blockIdx.x * blockDim.x + threadIdx.x;
    if (i >= npairs) return;
    float2 v = ((const float2*)x)[i];
    __nv_bfloat16 h0 = __float2bfloat16(v.x);
    __nv_bfloat16 h1 = __float2bfloat16(v.y);
    __nv_bfloat16 l0 = __float2bfloat16(v.x - __bfloat162float(h0));
    __nv_bfloat16 l1 = __float2bfloat16(v.y - __bfloat162float(h1));
    ((__nv_bfloat162*)g_xh)[i] = __nv_bfloat162(h0, h1);
    ((__nv_bfloat162*)g_xl)[i] = __nv_bfloat162(l0, l1);
}

// ---------------- W' = [W_l ; W_r] -> TRANSPOSED [64 k][128 n] bf16 hi/lo ----------------
__global__ void wsplit_k(const float* __restrict__ W1l, const float* __restrict__ W1r,
                         const float* __restrict__ W2l, const float* __restrict__ W2r) {
    int id = blockIdx.x * blockDim.x + threadIdx.x;
    if (id >= 16384) return;
    int l = id >> 13;
    int rem = id & 8191;
    int nr = rem >> 6;    // 0..127 output row of W'
    int k = rem & 63;     // 0..63 input col
    const float* Wl = l ? W2l : W1l;
    const float* Wr = l ? W2r : W1r;
    float w = (nr < 64) ? Wl[nr * 64 + k] : Wr[(nr - 64) * 64 + k];
    __nv_bfloat16 hi = __float2bfloat16(w);
    __nv_bfloat16 lo = __float2bfloat16(w - __bfloat162float(hi));
    g_wth[l][k * 128 + nr] = hi;     // transposed store
    g_wtl[l][k * 128 + nr] = lo;
}

// ---------------- WMMA GEMM: y[m0:m0+128][0:128] = A(hi,lo) @ W'(hi,lo)^T ----------------
// 3-term compensated bf16: Ah*Wh + Ah*Wl + Al*Wh, fp32 accumulation.
// 256 threads = 8 warps; warp w computes rows [m0+16w, m0+16w+16) x 128 cols.
// A fragments loaded straight from global bf16 (8 per warp, L1-resident rows).
// W staged in smem pitch 136 (68 words = 4 mod 32 -> conflict-free ldmatrix).
#define WP 136

template <int L>
__global__ void __launch_bounds__(256)
gemm_k(int n) {
    __shared__ __nv_bfloat16 Wh_s[64 * WP];
    __shared__ __nv_bfloat16 Wl_s[64 * WP];
    __shared__ float C_s[8 * 256];   // boundary staging only

    int tid = threadIdx.x;
    int w = tid >> 5;
    int lane = tid & 31;
    int m0 = blockIdx.x * 128;

    // stage W tiles (each 64 rows x 128 bf16 = 64 u32/row)
    {
        const uint32_t* __restrict__ sh = (const uint32_t*)g_wth[L];
        const uint32_t* __restrict__ sl = (const uint32_t*)g_wtl[L];
        uint32_t* dh = (uint32_t*)Wh_s;
        uint32_t* dl = (uint32_t*)Wl_s;
#pragma unroll
        for (int idx = tid; idx < 4096; idx += 256) {
            int row = idx >> 6;
            int c = idx & 63;
            dh[row * (WP / 2) + c] = sh[idx];
            dl[row * (WP / 2) + c] = sl[idx];
        }
    }
    __syncthreads();

    const __nv_bfloat16* __restrict__ Ah = (L ? g_hh : g_xh);
    const __nv_bfloat16* __restrict__ Al = (L ? g_hl : g_xl);
    int r0 = m0 + w * 16;
    const __nv_bfloat16* arow_h = Ah + (size_t)r0 * 64;
    const __nv_bfloat16* arow_l = Al + (size_t)r0 * 64;

    wmma::fragment<wmma::accumulator, 16, 16, 16, float> acc[8];
#pragma unroll
    for (int nt = 0; nt < 8; nt++) wmma::fill_fragment(acc[nt], 0.0f);

#pragma unroll
    for (int kt = 0; kt < 4; kt++) {
        wmma::fragment<wmma::matrix_a, 16, 16, 16, __nv_bfloat16, wmma::row_major> ah, al;
        wmma::load_matrix_sync(ah, arow_h + kt * 16, 64);
        wmma::load_matrix_sync(al, arow_l + kt * 16, 64);
#pragma unroll
        for (int nt = 0; nt < 8; nt++) {
            wmma::fragment<wmma::matrix_b, 16, 16, 16, __nv_bfloat16, wmma::row_major> bh, bl;
            wmma::load_matrix_sync(bh, &Wh_s[(kt * 16) * WP + nt * 16], WP);
            wmma::load_matrix_sync(bl, &Wl_s[(kt * 16) * WP + nt * 16], WP);
            wmma::mma_sync(acc[nt], ah, bh, acc[nt]);
            wmma::mma_sync(acc[nt], ah, bl, acc[nt]);
            wmma::mma_sync(acc[nt], al, bh, acc[nt]);
        }
    }

    if (r0 + 16 <= n) {
        // fast path: direct stores
#pragma unroll
        for (int nt = 0; nt < 8; nt++) {
            float* base = ((nt < 4) ? g_yl : g_yr) + (size_t)r0 * 64 + (nt & 3) * 16;
            wmma::store_matrix_sync(base, acc[nt], 64, wmma::mem_row_major);
        }
    } else if (r0 < n) {
        // boundary: stage per-warp, guarded copy
        float* stage = C_s + w * 256;
#pragma unroll
        for (int nt = 0; nt < 8; nt++) {
            wmma::store_matrix_sync(stage, acc[nt], 16, wmma::mem_row_major);
            __syncwarp();
            float* base = ((nt < 4) ? g_yl : g_yr);
#pragma unroll
            for (int q = 0; q < 8; q++) {
                int idx = lane * 8 + q;
                int row = idx >> 4;
                int col = idx & 15;
                int gm = r0 + row;
                if (gm < n) base[(size_t)gm * 64 + (nt & 3) * 16 + col] = stage[idx];
            }
            __syncwarp();
        }
    }
}

// ---------------- aggregation + epilogue: warp per node ----------------
// val = mean-gather(g_yl) + g_yr[own] + bias; L=0: relu + bf16 hi/lo split, L=1: fp32 out
template <int L>
__global__ void __launch_bounds__(256)
aggf_k(const float* __restrict__ bias, float* __restrict__ outp, int n) {
    int w = (blockIdx.x * 256 + threadIdx.x) >> 5;
    int lane = threadIdx.x & 31;
    if (w >= n) return;
    int beg = g_rowptr[w], end = g_rowptr[w + 1];
    float a0 = 0.f, a1 = 0.f;
    int p = beg;
    for (; p + 3 < end; p += 4) {
        int s0 = g_csr[p], s1 = g_csr[p + 1], s2 = g_csr[p + 2], s3 = g_csr[p + 3];
        const float* r0 = g_yl + (size_t)s0 * 64;
        const float* r1 = g_yl + (size_t)s1 * 64;
        const float* r2 = g_yl + (size_t)s2 * 64;
        const float* r3 = g_yl + (size_t)s3 * 64;
        a0 += (r0[lane] + r1[lane]) + (r2[lane] + r3[lane]);
        a1 += (r0[lane + 32] + r1[lane + 32]) + (r2[lane + 32] + r3[lane + 32]);
    }
    for (; p < end; p++) {
        const float* r = g_yl + (size_t)g_csr[p] * 64;
        a0 += r[lane];
        a1 += r[lane + 32];
    }
    int deg = end - beg;
    float inv = (deg > 0) ? (1.f / (float)deg) : 0.f;
    float v0 = fmaf(a0, inv, g_yr[(size_t)w * 64 + lane] + bias[lane]);
    float v1 = fmaf(a1, inv, g_yr[(size_t)w * 64 + 32 + lane] + bias[lane + 32]);
    if (L == 0) {
        v0 = fmaxf(v0, 0.f);
        v1 = fmaxf(v1, 0.f);
        __nv_bfloat16 h0 = __float2bfloat16(v0);
        __nv_bfloat16 h1 = __float2bfloat16(v1);
        g_hh[(size_t)w * 64 + lane] = h0;
        g_hh[(size_t)w * 64 + 32 + lane] = h1;
        g_hl[(size_t)w * 64 + lane] = __float2bfloat16(v0 - __bfloat162float(h0));
        g_hl[(size_t)w * 64 + 32 + lane] = __float2bfloat16(v1 - __bfloat162float(h1));
    } else {
        outp[(size_t)w * 64 + lane] = v0;
        outp[(size_t)w * 64 + 32 + lane] = v1;
    }
}

// ---------------- launcher ----------------
extern "C" void kernel_launch(void* const* d_in, const int* in_sizes, int n_in,
                              void* d_out, int out_size) {
    const float* x   = (const float*)d_in[0];
    const int*   ei  = (const int*)d_in[1];   // int32 (JAX x64 disabled)
    const float* W1l = (const float*)d_in[2];
    const float* b1  = (const float*)d_in[3];
    const float* W1r = (const float*)d_in[4];
    const float* W2l = (const float*)d_in[5];
    const float* b2  = (const float*)d_in[6];
    const float* W2r = (const float*)d_in[7];
    float* out = (float*)d_out;

    int n = in_sizes[0] / 64;
    int e = in_sizes[1] / 2;
    if (n > N_MAX) n = N_MAX;
    if (e > E_MAX) e = E_MAX;

    const int* src = ei;
    const int* dst = ei + e;
    int nb = (n + 1023) / 1024;
    int gg = (n + 127) / 128;
    int ga = (n + 7) / 8;

    // NOTE: launch order places gemm_k<0> at slot 4 so ncu (-s 5 -c 1) captures it.
    // gemm0 depends only on conv + wsplit; CSR build is independent of it.
    conv_k<<<(n * 32 + 255) / 256, 256>>>(x, n * 32);          // 1
    wsplit_k<<<64, 256>>>(W1l, W1r, W2l, W2r);                 // 2
    zero_k<<<(n + 255) / 256, 256>>>(n);                       // 3
    gemm_k<0><<<gg, 256>>>(n);                                 // 4  <- profiled
    count_k<<<(e + 255) / 256, 256>>>(dst, e, n);              // 5
    scan1_k<<<nb, 256>>>(n);                                   // 6
    scan23_k<<<nb, 256>>>(n, e);                               // 7
    fill_k<<<(e + 255) / 256, 256>>>(src, dst, e, n);          // 8

    // Layer 1 epilogue: h = relu(mean-gather(yl) + yr + b1) -> bf16 split
    aggf_k<0><<<ga, 256>>>(b1, nullptr, n);                    // 9
    // Layer 2
    gemm_k<1><<<gg, 256>>>(n);                                 // 10
    aggf_k<1><<<ga, 256>>>(b2, out, n);                        // 11
}

// round 10
// speedup vs baseline: 1.0453x; 1.0453x over previous
#include <cuda_runtime.h>
#include <cuda_bf16.h>
#include <mma.h>
#include <cstdint>

using namespace nvcuda;

#define N_MAX 100000
#define E_MAX 1000000
#define NB_MAX 128            // ceil(N_MAX/1024) = 98

// ---------------- device scratch (static; device-side references only) ----------------
__device__ int g_cnt[N_MAX];
__device__ int g_rowptr[N_MAX + 1];
__device__ int g_cursor[N_MAX];
__device__ int g_csr[E_MAX];
__device__ int g_bsum[NB_MAX];
__device__ __nv_bfloat16 g_hh[(size_t)N_MAX * 64];
__device__ __nv_bfloat16 g_hl[(size_t)N_MAX * 64];
__device__ float g_yl[(size_t)N_MAX * 64];   // lin_l projection (gathered by agg)
__device__ float g_yr[(size_t)N_MAX * 64];   // lin_r projection (root)
// W' = [W_l;W_r] TRANSPOSED: [64 k][128 n] row-major, bf16 hi/lo
__device__ __align__(16) __nv_bfloat16 g_wth[2][8192];
__device__ __align__(16) __nv_bfloat16 g_wtl[2][8192];

// ---------------- CSR build ----------------
__global__ void zero_k(int n) {
    int i = blockIdx.x * blockDim.x + threadIdx.x;
    if (i < n) g_cnt[i] = 0;
}

__global__ void count_k(const int* __restrict__ dst, int e, int n) {
    int i = blockIdx.x * blockDim.x + threadIdx.x;
    if (i < e) {
        int d = dst[i];
        if ((unsigned)d < (unsigned)n) atomicAdd(&g_cnt[d], 1);
    }
}

__global__ void scan1_k(int n) {
    int base = blockIdx.x * 1024;
    int t = threadIdx.x;
    int i0 = base + t * 4;
    int s = 0;
#pragma unroll
    for (int j = 0; j < 4; j++) {
        int i = i0 + j;
        if (i < n) s += g_cnt[i];
    }
#pragma unroll
    for (int o = 16; o; o >>= 1) s += __shfl_down_sync(0xffffffffu, s, o);
    __shared__ int ws[8];
    if ((t & 31) == 0) ws[t >> 5] = s;
    __syncthreads();
    if (t == 0) {
        int tot = 0;
#pragma unroll
        for (int j = 0; j < 8; j++) tot += ws[j];
        g_bsum[blockIdx.x] = tot;
    }
}

// merged scan2+scan3: each block derives its exclusive base from g_bsum itself
__global__ void scan23_k(int n, int e) {
    int t = threadIdx.x;
    int bid = blockIdx.x;
    int val = (t < bid) ? g_bsum[t] : 0;   // bid <= 97 < 256
#pragma unroll
    for (int o = 16; o; o >>= 1) val += __shfl_down_sync(0xffffffffu, val, o);
    __shared__ int wsb[8];
    __shared__ int s_base;
    if ((t & 31) == 0) wsb[t >> 5] = val;
    __syncthreads();
    if (t == 0) {
        int b = 0;
#pragma unroll
        for (int j = 0; j < 8; j++) b += wsb[j];
        s_base = b;
        if (bid == 0) g_rowptr[n] = e;
    }
    __syncthreads();
    int base = s_base;

    int lane = t & 31, wid = t >> 5;
    int i0 = bid * 1024 + t * 4;
    int v[4];
    int tsum = 0;
#pragma unroll
    for (int j = 0; j < 4; j++) {
        v[j] = (i0 + j < n) ? g_cnt[i0 + j] : 0;
        tsum += v[j];
    }
    int incl = tsum;
#pragma unroll
    for (int o = 1; o < 32; o <<= 1) {
        int u = __shfl_up_sync(0xffffffffu, incl, o);
        if (lane >= o) incl += u;
    }
    __shared__ int ws[8];
    if (lane == 31) ws[wid] = incl;
    __syncthreads();
    if (t < 8) {
        int u = ws[t];
        int inc = u;
#pragma unroll
        for (int o = 1; o < 8; o <<= 1) {
            int q = __shfl_up_sync(0xffu, inc, o);
            if (t >= o) inc += q;
        }
        ws[t] = inc - u;
    }
    __syncthreads();
    int excl = incl - tsum + ws[wid] + base;
#pragma unroll
    for (int j = 0; j < 4; j++) {
        int i = i0 + j;
        if (i < n) {
            g_rowptr[i] = excl;
            g_cursor[i] = excl;
            excl += v[j];
        }
    }
}

__global__ void fill_k(const int* __restrict__ src, const int* __restrict__ dst, int e, int n) {
    int i = blockIdx.x * blockDim.x + threadIdx.x;
    if (i < e) {
        int d = dst[i];
        int s = src[i];
        if ((unsigned)d < (unsigned)n && (unsigned)s < (unsigned)n) {
            int pos = atomicAdd(&g_cursor[d], 1);
            g_csr[pos] = s;
        }
    }
}

// ---------------- W' = [W_l ; W_r] -> TRANSPOSED [64 k][128 n] bf16 hi/lo ----------------
__global__ void wsplit_k(const float* __restrict__ W1l, const float* __restrict__ W1r,
                         const float* __restrict__ W2l, const float* __restrict__ W2r) {
    int id = blockIdx.x * blockDim.x + threadIdx.x;
    if (id >= 16384) return;
    int l = id >> 13;
    int rem = id & 8191;
    int nr = rem >> 6;    // 0..127 output row of W'
    int k = rem & 63;     // 0..63 input col
    const float* Wl = l ? W2l : W1l;
    const float* Wr = l ? W2r : W1r;
    float w = (nr < 64) ? Wl[nr * 64 + k] : Wr[(nr - 64) * 64 + k];
    __nv_bfloat16 hi = __float2bfloat16(w);
    __nv_bfloat16 lo = __float2bfloat16(w - __bfloat162float(hi));
    g_wth[l][k * 128 + nr] = hi;     // transposed store
    g_wtl[l][k * 128 + nr] = lo;
}

// ---------------- WMMA GEMM: y[m0:m0+32][0:128] = A(hi,lo) @ W'(hi,lo)^T ----------------
// 3-term compensated bf16: Ah*Wh + Ah*Wl + Al*Wh, fp32 accumulation.
// Block = 32 rows x 128 cols, 256 threads = 8 warps.
// Warp w: row strip s = w>>2 (16 rows), col quarter q = w&3 (32 cols) -> acc[2].
// L=0: A staged from fp32 x with fused hi/lo split. L=1: A from g_hh/g_hl.
// Pitches: A 72 bf16 (144B, 16B-aligned, conflict-free LDSM), W 136 bf16 (272B).
#define AP 72
#define WP 136

template <int L>
__global__ void __launch_bounds__(256, 4)
gemm_k(const float* __restrict__ x, int n) {
    __shared__ __nv_bfloat16 A_s[2][32 * AP];   // [hi/lo][row][k], also reused as epilogue scratch
    __shared__ __nv_bfloat16 Wh_s[64 * WP];
    __shared__ __nv_bfloat16 Wl_s[64 * WP];

    int tid = threadIdx.x;
    int w = tid >> 5;
    int lane = tid & 31;
    int m0 = blockIdx.x * 32;

    // stage W tiles: 64 rows x 128 bf16 = 16 uint4/row, 1024 uint4 per matrix
    {
        const uint4* __restrict__ sh = (const uint4*)g_wth[L];
        const uint4* __restrict__ sl = (const uint4*)g_wtl[L];
#pragma unroll
        for (int i = 0; i < 8; i++) {
            int idx = tid + i * 256;          // 0..2047
            int mat = idx >> 10;              // 0: hi, 1: lo
            int r = (idx & 1023) >> 4;        // row 0..63
            int q4 = idx & 15;                // 16B chunk
            uint4 v = (mat ? sl : sh)[(idx & 1023)];
            __nv_bfloat16* dstbase = mat ? Wl_s : Wh_s;
            *(uint4*)(dstbase + r * WP + q4 * 8) = v;
        }
    }

    // stage A tile (32 rows x 64 k), hi/lo split
    if (L == 0) {
        // read fp32 x directly, split in-register (fused conv)
#pragma unroll
        for (int i = 0; i < 8; i++) {
            int idx = tid + i * 256;          // 0..2047
            int row = idx >> 6;
            int c = idx & 63;
            int gm = m0 + row;
            float v = (gm < n) ? x[(size_t)gm * 64 + c] : 0.f;
            __nv_bfloat16 hi = __float2bfloat16(v);
            A_s[0][row * AP + c] = hi;
            A_s[1][row * AP + c] = __float2bfloat16(v - __bfloat162float(hi));
        }
    } else {
        const uint32_t* __restrict__ sh = (const uint32_t*)g_hh;
        const uint32_t* __restrict__ sl = (const uint32_t*)g_hl;
#pragma unroll
        for (int i = 0; i < 4; i++) {
            int idx = tid + i * 256;          // 0..1023
            int row = idx >> 5;
            int c = idx & 31;
            int gm = m0 + row;
            uint32_t vh = 0u, vl = 0u;
            if (gm < n) {
                vh = sh[(size_t)gm * 32 + c];
                vl = sl[(size_t)gm * 32 + c];
            }
            ((uint32_t*)A_s[0])[row * (AP / 2) + c] = vh;
            ((uint32_t*)A_s[1])[row * (AP / 2) + c] = vl;
        }
    }
    __syncthreads();

    int s = w >> 2;           // row strip 0/1
    int q = w & 3;            // col quarter 0..3
    int r0 = m0 + s * 16;

    wmma::fragment<wmma::accumulator, 16, 16, 16, float> acc[2];
    wmma::fill_fragment(acc[0], 0.0f);
    wmma::fill_fragment(acc[1], 0.0f);

#pragma unroll
    for (int kt = 0; kt < 4; kt++) {
        wmma::fragment<wmma::matrix_a, 16, 16, 16, __nv_bfloat16, wmma::row_major> ah, al;
        wmma::load_matrix_sync(ah, &A_s[0][(s * 16) * AP + kt * 16], AP);
        wmma::load_matrix_sync(al, &A_s[1][(s * 16) * AP + kt * 16], AP);
#pragma unroll
        for (int nt = 0; nt < 2; nt++) {
            int col = q * 32 + nt * 16;
            wmma::fragment<wmma::matrix_b, 16, 16, 16, __nv_bfloat16, wmma::row_major> bh, bl;
            wmma::load_matrix_sync(bh, &Wh_s[(kt * 16) * WP + col], WP);
            wmma::load_matrix_sync(bl, &Wl_s[(kt * 16) * WP + col], WP);
            wmma::mma_sync(acc[nt], ah, bh, acc[nt]);
            wmma::mma_sync(acc[nt], ah, bl, acc[nt]);
            wmma::mma_sync(acc[nt], al, bh, acc[nt]);
        }
    }

    if (r0 + 16 <= n) {
        // fast path (always taken for n % 32 == 0)
#pragma unroll
        for (int nt = 0; nt < 2; nt++) {
            int col = q * 32 + nt * 16;
            float* base = (col < 64) ? (g_yl + (size_t)r0 * 64 + col)
                                     : (g_yr + (size_t)r0 * 64 + (col - 64));
            wmma::store_matrix_sync(base, acc[nt], 64, wmma::mem_row_major);
        }
    } else if (m0 < n) {
        // boundary: reuse A_s as scratch (whole block reaches here together)
        __syncthreads();
        float* scratch = (float*)A_s + w * 256;   // 8 warps x 1KB <= 18KB
#pragma unroll
        for (int nt = 0; nt < 2; nt++) {
            int col = q * 32 + nt * 16;
            wmma::store_matrix_sync(scratch, acc[nt], 16, wmma::mem_row_major);
            __syncwarp();
            float* base = (col < 64) ? g_yl : g_yr;
            int cb = (col < 64) ? col : col - 64;
#pragma unroll
            for (int i = 0; i < 8; i++) {
                int idx = lane * 8 + i;
                int row = idx >> 4;
                int cc = idx & 15;
                int gm = r0 + row;
                if (gm < n) base[(size_t)gm * 64 + cb + cc] = scratch[idx];
            }
            __syncwarp();
        }
    }
}

// ---------------- aggregation + epilogue: warp per node ----------------
// val = mean-gather(g_yl) + g_yr[own] + bias; L=0: relu + bf16 hi/lo split, L=1: fp32 out
template <int L>
__global__ void __launch_bounds__(256)
aggf_k(const float* __restrict__ bias, float* __restrict__ outp, int n) {
    int w = (blockIdx.x * 256 + threadIdx.x) >> 5;
    int lane = threadIdx.x & 31;
    if (w >= n) return;
    int beg = g_rowptr[w], end = g_rowptr[w + 1];
    float a0 = 0.f, a1 = 0.f;
    int p = beg;
    for (; p + 3 < end; p += 4) {
        int s0 = g_csr[p], s1 = g_csr[p + 1], s2 = g_csr[p + 2], s3 = g_csr[p + 3];
        const float* r0 = g_yl + (size_t)s0 * 64;
        const float* r1 = g_yl + (size_t)s1 * 64;
        const float* r2 = g_yl + (size_t)s2 * 64;
        const float* r3 = g_yl + (size_t)s3 * 64;
        a0 += (r0[lane] + r1[lane]) + (r2[lane] + r3[lane]);
        a1 += (r0[lane + 32] + r1[lane + 32]) + (r2[lane + 32] + r3[lane + 32]);
    }
    for (; p < end; p++) {
        const float* r = g_yl + (size_t)g_csr[p] * 64;
        a0 += r[lane];
        a1 += r[lane + 32];
    }
    int deg = end - beg;
    float inv = (deg > 0) ? (1.f / (float)deg) : 0.f;
    float v0 = fmaf(a0, inv, g_yr[(size_t)w * 64 + lane] + bias[lane]);
    float v1 = fmaf(a1, inv, g_yr[(size_t)w * 64 + 32 + lane] + bias[lane + 32]);
    if (L == 0) {
        v0 = fmaxf(v0, 0.f);
        v1 = fmaxf(v1, 0.f);
        __nv_bfloat16 h0 = __float2bfloat16(v0);
        __nv_bfloat16 h1 = __float2bfloat16(v1);
        g_hh[(size_t)w * 64 + lane] = h0;
        g_hh[(size_t)w * 64 + 32 + lane] = h1;
        g_hl[(size_t)w * 64 + lane] = __float2bfloat16(v0 - __bfloat162float(h0));
        g_hl[(size_t)w * 64 + 32 + lane] = __float2bfloat16(v1 - __bfloat162float(h1));
    } else {
        outp[(size_t)w * 64 + lane] = v0;
        outp[(size_t)w * 64 + 32 + lane] = v1;
    }
}

// ---------------- launcher ----------------
extern "C" void kernel_launch(void* const* d_in, const int* in_sizes, int n_in,
                              void* d_out, int out_size) {
    const float* x   = (const float*)d_in[0];
    const int*   ei  = (const int*)d_in[1];   // int32 (JAX x64 disabled)
    const float* W1l = (const float*)d_in[2];
    const float* b1  = (const float*)d_in[3];
    const float* W1r = (const float*)d_in[4];
    const float* W2l = (const float*)d_in[5];
    const float* b2  = (const float*)d_in[6];
    const float* W2r = (const float*)d_in[7];
    float* out = (float*)d_out;

    int n = in_sizes[0] / 64;
    int e = in_sizes[1] / 2;
    if (n > N_MAX) n = N_MAX;
    if (e > E_MAX) e = E_MAX;

    const int* src = ei;
    const int* dst = ei + e;
    int nb = (n + 1023) / 1024;
    int gg = (n + 31) / 32;
    int ga = (n + 7) / 8;

    // Launch order keeps gemm_k<0> at slot 4 for ncu (-s 5 -c 1) capture.
    wsplit_k<<<64, 256>>>(W1l, W1r, W2l, W2r);                 // 1
    zero_k<<<(n + 255) / 256, 256>>>(n);                       // 2
    count_k<<<(e + 255) / 256, 256>>>(dst, e, n);              // 3
    gemm_k<0><<<gg, 256>>>(x, n);                              // 4  <- profiled
    scan1_k<<<nb, 256>>>(n);                                   // 5
    scan23_k<<<nb, 256>>>(n, e);                               // 6
    fill_k<<<(e + 255) / 256, 256>>>(src, dst, e, n);          // 7

    // Layer 1 epilogue: h = relu(mean-gather(yl) + yr + b1) -> bf16 split
    aggf_k<0><<<ga, 256>>>(b1, nullptr, n);                    // 8
    // Layer 2
    gemm_k<1><<<gg, 256>>>(x, n);                              // 9
    aggf_k<1><<<ga, 256>>>(b2, out, n);                        // 10
}

// round 12
// speedup vs baseline: 1.0822x; 1.0353x over previous
#include <cuda_runtime.h>
#include <cuda_bf16.h>
#include <mma.h>
#include <cstdint>

using namespace nvcuda;

#define N_MAX 100000
#define E_MAX 1000000
#define NB_MAX 128            // ceil(N_MAX/1024) = 98

// ---------------- device scratch (static; device-side references only) ----------------
__device__ int g_cnt[N_MAX];
__device__ int g_rowptr[N_MAX + 1];
__device__ int g_cursor[N_MAX];
__device__ int g_csr[E_MAX];
__device__ int g_bsum[NB_MAX];
__device__ __nv_bfloat16 g_hh[(size_t)N_MAX * 64];
__device__ __nv_bfloat16 g_hl[(size_t)N_MAX * 64];
__device__ float g_yl[(size_t)N_MAX * 64];   // lin_l projection (gathered by agg)
__device__ float g_yr[(size_t)N_MAX * 64];   // lin_r projection (root)
// W' = [W_l;W_r] TRANSPOSED: [64 k][128 n] row-major, bf16 hi/lo
__device__ __align__(16) __nv_bfloat16 g_wth[2][8192];
__device__ __align__(16) __nv_bfloat16 g_wtl[2][8192];

// ---------------- CSR build ----------------
__global__ void zero_k(int n) {
    int i = blockIdx.x * blockDim.x + threadIdx.x;
    if (i < n) g_cnt[i] = 0;
}

__global__ void count_k(const int* __restrict__ dst, int e, int n) {
    int i = blockIdx.x * blockDim.x + threadIdx.x;
    if (i < e) {
        int d = dst[i];
        if ((unsigned)d < (unsigned)n) atomicAdd(&g_cnt[d], 1);
    }
}

__global__ void scan1_k(int n) {
    int base = blockIdx.x * 1024;
    int t = threadIdx.x;
    int i0 = base + t * 4;
    int s = 0;
#pragma unroll
    for (int j = 0; j < 4; j++) {
        int i = i0 + j;
        if (i < n) s += g_cnt[i];
    }
#pragma unroll
    for (int o = 16; o; o >>= 1) s += __shfl_down_sync(0xffffffffu, s, o);
    __shared__ int ws[8];
    if ((t & 31) == 0) ws[t >> 5] = s;
    __syncthreads();
    if (t == 0) {
        int tot = 0;
#pragma unroll
        for (int j = 0; j < 8; j++) tot += ws[j];
        g_bsum[blockIdx.x] = tot;
    }
}

// merged scan2+scan3: each block derives its exclusive base from g_bsum itself
__global__ void scan23_k(int n, int e) {
    int t = threadIdx.x;
    int bid = blockIdx.x;
    int val = (t < bid) ? g_bsum[t] : 0;   // bid <= 97 < 256
#pragma unroll
    for (int o = 16; o; o >>= 1) val += __shfl_down_sync(0xffffffffu, val, o);
    __shared__ int wsb[8];
    __shared__ int s_base;
    if ((t & 31) == 0) wsb[t >> 5] = val;
    __syncthreads();
    if (t == 0) {
        int b = 0;
#pragma unroll
        for (int j = 0; j < 8; j++) b += wsb[j];
        s_base = b;
        if (bid == 0) g_rowptr[n] = e;
    }
    __syncthreads();
    int base = s_base;

    int lane = t & 31, wid = t >> 5;
    int i0 = bid * 1024 + t * 4;
    int v[4];
    int tsum = 0;
#pragma unroll
    for (int j = 0; j < 4; j++) {
        v[j] = (i0 + j < n) ? g_cnt[i0 + j] : 0;
        tsum += v[j];
    }
    int incl = tsum;
#pragma unroll
    for (int o = 1; o < 32; o <<= 1) {
        int u = __shfl_up_sync(0xffffffffu, incl, o);
        if (lane >= o) incl += u;
    }
    __shared__ int ws[8];
    if (lane == 31) ws[wid] = incl;
    __syncthreads();
    if (t < 8) {
        int u = ws[t];
        int inc = u;
#pragma unroll
        for (int o = 1; o < 8; o <<= 1) {
            int q = __shfl_up_sync(0xffu, inc, o);
            if (t >= o) inc += q;
        }
        ws[t] = inc - u;
    }
    __syncthreads();
    int excl = incl - tsum + ws[wid] + base;
#pragma unroll
    for (int j = 0; j < 4; j++) {
        int i = i0 + j;
        if (i < n) {
            g_rowptr[i] = excl;
            g_cursor[i] = excl;
            excl += v[j];
        }
    }
}

__global__ void fill_k(const int* __restrict__ src, const int* __restrict__ dst, int e, int n) {
    int i = blockIdx.x * blockDim.x + threadIdx.x;
    if (i < e) {
        int d = dst[i];
        int s = src[i];
        if ((unsigned)d < (unsigned)n && (unsigned)s < (unsigned)n) {
            int pos = atomicAdd(&g_cursor[d], 1);
            g_csr[pos] = s;
        }
    }
}

// ---------------- W' = [W_l ; W_r] -> TRANSPOSED [64 k][128 n] bf16 hi/lo ----------------
__global__ void wsplit_k(const float* __restrict__ W1l, const float* __restrict__ W1r,
                         const float* __restrict__ W2l, const float* __restrict__ W2r) {
    int id = blockIdx.x * blockDim.x + threadIdx.x;
    if (id >= 16384) return;
    int l = id >> 13;
    int rem = id & 8191;
    int nr = rem >> 6;    // 0..127 output row of W'
    int k = rem & 63;     // 0..63 input col
    const float* Wl = l ? W2l : W1l;
    const float* Wr = l ? W2r : W1r;
    float w = (nr < 64) ? Wl[nr * 64 + k] : Wr[(nr - 64) * 64 + k];
    __nv_bfloat16 hi = __float2bfloat16(w);
    __nv_bfloat16 lo = __float2bfloat16(w - __bfloat162float(hi));
    g_wth[l][k * 128 + nr] = hi;     // transposed store
    g_wtl[l][k * 128 + nr] = lo;
}

// ---------------- WMMA GEMM: y[m0:m0+64][c0:c0+64] = A(hi,lo) @ W'(hi,lo)^T ----------------
// 3-term compensated bf16: Ah*Wh + Ah*Wl + Al*Wh, fp32 accumulation.
// Grid (ceil(n/64), 2): blockIdx.y = column half (0 -> y_l, 1 -> y_r).
// 256 threads = 8 warps; warp w: row strip s=w>>1 (16 rows), col strip q=w&1 (32 cols), acc[2].
// Pitches 72 bf16 (144B) -> conflict-free ldmatrix. Static smem ~45KB.
#define AP 72
#define WP 72

template <int L>
__global__ void __launch_bounds__(256, 4)
gemm_k(const float* __restrict__ x, int n) {
    __shared__ __nv_bfloat16 A_s[2][64 * AP];
    __shared__ __nv_bfloat16 Wh_s[64 * WP];
    __shared__ __nv_bfloat16 Wl_s[64 * WP];
    __shared__ float C_s[8 * 256];   // boundary staging (per-warp, __syncwarp only)

    int tid = threadIdx.x;
    int w = tid >> 5;
    int lane = tid & 31;
    int m0 = blockIdx.x * 64;
    int c0 = blockIdx.y * 64;

    // stage W tile: 64 k-rows x 64 cols (hi+lo), 8 uint4 per row each
    {
        const __nv_bfloat16* __restrict__ sh = g_wth[L];
        const __nv_bfloat16* __restrict__ sl = g_wtl[L];
#pragma unroll
        for (int i = 0; i < 4; i++) {
            int idx = tid + i * 256;           // 0..1023
            int mat = idx >> 9;                // 0 hi, 1 lo
            int r = (idx & 511) >> 3;          // 0..63
            int q4 = idx & 7;                  // 16B chunk
            uint4 v = ((const uint4*)((mat ? sl : sh) + r * 128 + c0))[q4];
            *(uint4*)((mat ? Wl_s : Wh_s) + r * WP + q4 * 8) = v;
        }
    }

    // stage A tile (64 rows x 64 k), hi/lo split
    if (L == 0) {
        // read fp32 x directly, split in-register (fused conv)
#pragma unroll
        for (int i = 0; i < 16; i++) {
            int idx = tid + i * 256;           // 0..4095
            int row = idx >> 6;
            int c = idx & 63;
            int gm = m0 + row;
            float v = (gm < n) ? x[(size_t)gm * 64 + c] : 0.f;
            __nv_bfloat16 hi = __float2bfloat16(v);
            A_s[0][row * AP + c] = hi;
            A_s[1][row * AP + c] = __float2bfloat16(v - __bfloat162float(hi));
        }
    } else {
        const uint32_t* __restrict__ sh = (const uint32_t*)g_hh;
        const uint32_t* __restrict__ sl = (const uint32_t*)g_hl;
#pragma unroll
        for (int i = 0; i < 8; i++) {
            int idx = tid + i * 256;           // 0..2047
            int row = idx >> 5;
            int c = idx & 31;
            int gm = m0 + row;
            uint32_t vh = 0u, vl = 0u;
            if (gm < n) {
                vh = sh[(size_t)gm * 32 + c];
                vl = sl[(size_t)gm * 32 + c];
            }
            ((uint32_t*)A_s[0])[row * (AP / 2) + c] = vh;
            ((uint32_t*)A_s[1])[row * (AP / 2) + c] = vl;
        }
    }
    __syncthreads();

    int s = w >> 1;           // row strip 0..3
    int q = w & 1;            // col strip 0..1
    int r0 = m0 + s * 16;

    wmma::fragment<wmma::accumulator, 16, 16, 16, float> acc[2];
    wmma::fill_fragment(acc[0], 0.0f);
    wmma::fill_fragment(acc[1], 0.0f);

#pragma unroll
    for (int kt = 0; kt < 4; kt++) {
        wmma::fragment<wmma::matrix_a, 16, 16, 16, __nv_bfloat16, wmma::row_major> ah, al;
        wmma::load_matrix_sync(ah, &A_s[0][(s * 16) * AP + kt * 16], AP);
        wmma::load_matrix_sync(al, &A_s[1][(s * 16) * AP + kt * 16], AP);
#pragma unroll
        for (int nt = 0; nt < 2; nt++) {
            int col = q * 32 + nt * 16;
            wmma::fragment<wmma::matrix_b, 16, 16, 16, __nv_bfloat16, wmma::row_major> bh, bl;
            wmma::load_matrix_sync(bh, &Wh_s[(kt * 16) * WP + col], WP);
            wmma::load_matrix_sync(bl, &Wl_s[(kt * 16) * WP + col], WP);
            wmma::mma_sync(acc[nt], ah, bh, acc[nt]);
            wmma::mma_sync(acc[nt], ah, bl, acc[nt]);
            wmma::mma_sync(acc[nt], al, bh, acc[nt]);
        }
    }

    float* outbuf = blockIdx.y ? g_yr : g_yl;
    if (r0 + 16 <= n) {
        // fast path
#pragma unroll
        for (int nt = 0; nt < 2; nt++) {
            int col = q * 32 + nt * 16;
            wmma::store_matrix_sync(outbuf + (size_t)r0 * 64 + col, acc[nt], 64, wmma::mem_row_major);
        }
    } else if (r0 < n) {
        // boundary strip: per-warp scratch, no block sync (other warps may be on fast path)
        float* scratch = C_s + w * 256;
#pragma unroll
        for (int nt = 0; nt < 2; nt++) {
            int col = q * 32 + nt * 16;
            wmma::store_matrix_sync(scratch, acc[nt], 16, wmma::mem_row_major);
            __syncwarp();
#pragma unroll
            for (int i = 0; i < 8; i++) {
                int idx = lane * 8 + i;
                int row = idx >> 4;
                int cc = idx & 15;
                int gm = r0 + row;
                if (gm < n) outbuf[(size_t)gm * 64 + col + cc] = scratch[idx];
            }
            __syncwarp();
        }
    }
}

// ---------------- aggregation + epilogue: warp per node, float2 lanes ----------------
// lane owns cols {2*lane, 2*lane+1}. val = mean-gather(g_yl) + g_yr[own] + bias.
// L=0: relu + bf16 hi/lo split; L=1: fp32 out.
template <int L>
__global__ void __launch_bounds__(256)
aggf_k(const float* __restrict__ bias, float* __restrict__ outp, int n) {
    int w = (blockIdx.x * 256 + threadIdx.x) >> 5;
    int lane = threadIdx.x & 31;
    if (w >= n) return;
    int beg = g_rowptr[w], end = g_rowptr[w + 1];
    float a0 = 0.f, a1 = 0.f;
    int p = beg;
    for (; p + 3 < end; p += 4) {
        int s0 = g_csr[p], s1 = g_csr[p + 1], s2 = g_csr[p + 2], s3 = g_csr[p + 3];
        float2 v0 = ((const float2*)(g_yl + (size_t)s0 * 64))[lane];
        float2 v1 = ((const float2*)(g_yl + (size_t)s1 * 64))[lane];
        float2 v2 = ((const float2*)(g_yl + (size_t)s2 * 64))[lane];
        float2 v3 = ((const float2*)(g_yl + (size_t)s3 * 64))[lane];
        a0 += (v0.x + v1.x) + (v2.x + v3.x);
        a1 += (v0.y + v1.y) + (v2.y + v3.y);
    }
    for (; p < end; p++) {
        float2 v = ((const float2*)(g_yl + (size_t)g_csr[p] * 64))[lane];
        a0 += v.x;
        a1 += v.y;
    }
    int deg = end - beg;
    float inv = (deg > 0) ? (1.f / (float)deg) : 0.f;
    float2 yr = ((const float2*)(g_yr + (size_t)w * 64))[lane];
    float2 bb = ((const float2*)bias)[lane];
    float v0 = fmaf(a0, inv, yr.x + bb.x);
    float v1 = fmaf(a1, inv, yr.y + bb.y);
    if (L == 0) {
        v0 = fmaxf(v0, 0.f);
        v1 = fmaxf(v1, 0.f);
        __nv_bfloat16 h0 = __float2bfloat16(v0);
        __nv_bfloat16 h1 = __float2bfloat16(v1);
        ((__nv_bfloat162*)(g_hh + (size_t)w * 64))[lane] = __nv_bfloat162(h0, h1);
        ((__nv_bfloat162*)(g_hl + (size_t)w * 64))[lane] =
            __nv_bfloat162(__float2bfloat16(v0 - __bfloat162float(h0)),
                           __float2bfloat16(v1 - __bfloat162float(h1)));
    } else {
        ((float2*)(outp + (size_t)w * 64))[lane] = make_float2(v0, v1);
    }
}

// ---------------- launcher ----------------
extern "C" void kernel_launch(void* const* d_in, const int* in_sizes, int n_in,
                              void* d_out, int out_size) {
    const float* x   = (const float*)d_in[0];
    const int*   ei  = (const int*)d_in[1];   // int32 (JAX x64 disabled)
    const float* W1l = (const float*)d_in[2];
    const float* b1  = (const float*)d_in[3];
    const float* W1r = (const float*)d_in[4];
    const float* W2l = (const float*)d_in[5];
    const float* b2  = (const float*)d_in[6];
    const float* W2r = (const float*)d_in[7];
    float* out = (float*)d_out;

    int n = in_sizes[0] / 64;
    int e = in_sizes[1] / 2;
    if (n > N_MAX) n = N_MAX;
    if (e > E_MAX) e = E_MAX;

    const int* src = ei;
    const int* dst = ei + e;
    int nb = (n + 1023) / 1024;
    dim3 gg((n + 63) / 64, 2);
    int ga = (n + 7) / 8;

    // Launch order keeps gemm_k<0> at slot 4 for ncu (-s 5 -c 1) capture.
    wsplit_k<<<64, 256>>>(W1l, W1r, W2l, W2r);                 // 1
    zero_k<<<(n + 255) / 256, 256>>>(n);                       // 2
    count_k<<<(e + 255) / 256, 256>>>(dst, e, n);              // 3
    gemm_k<0><<<gg, 256>>>(x, n);                              // 4  <- profiled
    scan1_k<<<nb, 256>>>(n);                                   // 5
    scan23_k<<<nb, 256>>>(n, e);                               // 6
    fill_k<<<(e + 255) / 256, 256>>>(src, dst, e, n);          // 7

    // Layer 1 epilogue: h = relu(mean-gather(yl) + yr + b1) -> bf16 split
    aggf_k<0><<<ga, 256>>>(b1, nullptr, n);                    // 8
    // Layer 2
    gemm_k<1><<<gg, 256>>>(x, n);                              // 9
    aggf_k<1><<<ga, 256>>>(b2, out, n);                        // 10
}

// round 14
// speedup vs baseline: 1.1358x; 1.0496x over previous
#include <cuda_runtime.h>
#include <cuda_bf16.h>
#include <cuda_fp16.h>
#include <mma.h>
#include <cstdint>

using namespace nvcuda;

#define N_MAX 100000
#define E_MAX 1000000
#define NB_MAX 128            // ceil(N_MAX/1024) = 98

// ---------------- device scratch (static; device-side references only) ----------------
__device__ int g_cnt[N_MAX];
__device__ int g_rowptr[N_MAX + 1];
__device__ int g_cursor[N_MAX];
__device__ int g_csr[E_MAX];
__device__ int g_bsum[NB_MAX];
__device__ __nv_bfloat16 g_hh[(size_t)N_MAX * 64];
__device__ __nv_bfloat16 g_hl[(size_t)N_MAX * 64];
__device__ __half g_ylh[(size_t)N_MAX * 64];  // lin_l projection, fp16 (gathered by agg)
__device__ float g_yr[(size_t)N_MAX * 64];    // lin_r projection (root), fp32
// W' = [W_l;W_r] TRANSPOSED: [64 k][128 n] row-major, bf16 hi/lo
__device__ __align__(16) __nv_bfloat16 g_wth[2][8192];
__device__ __align__(16) __nv_bfloat16 g_wtl[2][8192];

// ---------------- CSR build ----------------
__global__ void zero_k(int n) {
    int i = blockIdx.x * blockDim.x + threadIdx.x;
    if (i < n) g_cnt[i] = 0;
}

__global__ void count_k(const int* __restrict__ dst, int e, int n) {
    int i = blockIdx.x * blockDim.x + threadIdx.x;
    if (i < e) {
        int d = dst[i];
        if ((unsigned)d < (unsigned)n) atomicAdd(&g_cnt[d], 1);
    }
}

__global__ void scan1_k(int n) {
    int base = blockIdx.x * 1024;
    int t = threadIdx.x;
    int i0 = base + t * 4;
    int s = 0;
#pragma unroll
    for (int j = 0; j < 4; j++) {
        int i = i0 + j;
        if (i < n) s += g_cnt[i];
    }
#pragma unroll
    for (int o = 16; o; o >>= 1) s += __shfl_down_sync(0xffffffffu, s, o);
    __shared__ int ws[8];
    if ((t & 31) == 0) ws[t >> 5] = s;
    __syncthreads();
    if (t == 0) {
        int tot = 0;
#pragma unroll
        for (int j = 0; j < 8; j++) tot += ws[j];
        g_bsum[blockIdx.x] = tot;
    }
}

// merged scan2+scan3: each block derives its exclusive base from g_bsum itself
__global__ void scan23_k(int n, int e) {
    int t = threadIdx.x;
    int bid = blockIdx.x;
    int val = (t < bid) ? g_bsum[t] : 0;   // bid <= 97 < 256
#pragma unroll
    for (int o = 16; o; o >>= 1) val += __shfl_down_sync(0xffffffffu, val, o);
    __shared__ int wsb[8];
    __shared__ int s_base;
    if ((t & 31) == 0) wsb[t >> 5] = val;
    __syncthreads();
    if (t == 0) {
        int b = 0;
#pragma unroll
        for (int j = 0; j < 8; j++) b += wsb[j];
        s_base = b;
        if (bid == 0) g_rowptr[n] = e;
    }
    __syncthreads();
    int base = s_base;

    int lane = t & 31, wid = t >> 5;
    int i0 = bid * 1024 + t * 4;
    int v[4];
    int tsum = 0;
#pragma unroll
    for (int j = 0; j < 4; j++) {
        v[j] = (i0 + j < n) ? g_cnt[i0 + j] : 0;
        tsum += v[j];
    }
    int incl = tsum;
#pragma unroll
    for (int o = 1; o < 32; o <<= 1) {
        int u = __shfl_up_sync(0xffffffffu, incl, o);
        if (lane >= o) incl += u;
    }
    __shared__ int ws[8];
    if (lane == 31) ws[wid] = incl;
    __syncthreads();
    if (t < 8) {
        int u = ws[t];
        int inc = u;
#pragma unroll
        for (int o = 1; o < 8; o <<= 1) {
            int q = __shfl_up_sync(0xffu, inc, o);
            if (t >= o) inc += q;
        }
        ws[t] = inc - u;
    }
    __syncthreads();
    int excl = incl - tsum + ws[wid] + base;
#pragma unroll
    for (int j = 0; j < 4; j++) {
        int i = i0 + j;
        if (i < n) {
            g_rowptr[i] = excl;
            g_cursor[i] = excl;
            excl += v[j];
        }
    }
}

__global__ void fill_k(const int* __restrict__ src, const int* __restrict__ dst, int e, int n) {
    int i = blockIdx.x * blockDim.x + threadIdx.x;
    if (i < e) {
        int d = dst[i];
        int s = src[i];
        if ((unsigned)d < (unsigned)n && (unsigned)s < (unsigned)n) {
            int pos = atomicAdd(&g_cursor[d], 1);
            g_csr[pos] = s;
        }
    }
}

// ---------------- W' = [W_l ; W_r] -> TRANSPOSED [64 k][128 n] bf16 hi/lo ----------------
__global__ void wsplit_k(const float* __restrict__ W1l, const float* __restrict__ W1r,
                         const float* __restrict__ W2l, const float* __restrict__ W2r) {
    int id = blockIdx.x * blockDim.x + threadIdx.x;
    if (id >= 16384) return;
    int l = id >> 13;
    int rem = id & 8191;
    int nr = rem >> 6;    // 0..127 output row of W'
    int k = rem & 63;     // 0..63 input col
    const float* Wl = l ? W2l : W1l;
    const float* Wr = l ? W2r : W1r;
    float w = (nr < 64) ? Wl[nr * 64 + k] : Wr[(nr - 64) * 64 + k];
    __nv_bfloat16 hi = __float2bfloat16(w);
    __nv_bfloat16 lo = __float2bfloat16(w - __bfloat162float(hi));
    g_wth[l][k * 128 + nr] = hi;     // transposed store
    g_wtl[l][k * 128 + nr] = lo;
}

// ---------------- WMMA GEMM: y[m0:m0+64][c0:c0+64] = A(hi,lo) @ W'(hi,lo)^T ----------------
// 3-term compensated bf16: Ah*Wh + Ah*Wl + Al*Wh, fp32 accumulation.
// Grid (ceil(n/64), 2): blockIdx.y = column half (0 -> y_l fp16, 1 -> y_r fp32).
// 128 threads = 4 warps; warp w: rows [m0+(w>>1)*32, +32) x cols [c0+(w&1)*32, +32); acc[2][2].
// Pitches 72 bf16 (144B) -> conflict-free ldmatrix. Static smem ~41KB.
#define AP 72
#define WP 72

template <int L>
__global__ void __launch_bounds__(128, 4)
gemm_k(const float* __restrict__ x, int n) {
    __shared__ __nv_bfloat16 A_s[2][64 * AP];
    __shared__ __nv_bfloat16 Wh_s[64 * WP];
    __shared__ __nv_bfloat16 Wl_s[64 * WP];
    __shared__ float C_s[4 * 256];   // per-warp 16x16 epilogue scratch

    int tid = threadIdx.x;
    int w = tid >> 5;
    int lane = tid & 31;
    int m0 = blockIdx.x * 64;
    int c0 = blockIdx.y * 64;

    // stage W tile: 64 k-rows x 64 cols (hi+lo), 8 uint4 per row each
    {
        const __nv_bfloat16* __restrict__ sh = g_wth[L];
        const __nv_bfloat16* __restrict__ sl = g_wtl[L];
#pragma unroll
        for (int i = 0; i < 8; i++) {
            int idx = tid + i * 128;           // 0..1023
            int mat = idx >> 9;                // 0 hi, 1 lo
            int rem = idx & 511;
            int r = rem >> 3;                  // 0..63
            int q4 = rem & 7;                  // 16B chunk
            uint4 v = ((const uint4*)((mat ? sl : sh) + r * 128 + c0))[q4];
            *(uint4*)((mat ? Wl_s : Wh_s) + r * WP + q4 * 8) = v;
        }
    }

    // stage A tile (64 rows x 64 k), hi/lo split
    if (L == 0) {
        // read fp32 x directly, split in-register (fused conv)
#pragma unroll
        for (int i = 0; i < 32; i++) {
            int idx = tid + i * 128;           // 0..4095
            int row = idx >> 6;
            int c = idx & 63;
            int gm = m0 + row;
            float v = (gm < n) ? x[(size_t)gm * 64 + c] : 0.f;
            __nv_bfloat16 hi = __float2bfloat16(v);
            A_s[0][row * AP + c] = hi;
            A_s[1][row * AP + c] = __float2bfloat16(v - __bfloat162float(hi));
        }
    } else {
        const uint32_t* __restrict__ sh = (const uint32_t*)g_hh;
        const uint32_t* __restrict__ sl = (const uint32_t*)g_hl;
#pragma unroll
        for (int i = 0; i < 32; i++) {
            int idx = tid + i * 128;           // 0..4095
            int mat = idx >> 11;
            int rem = idx & 2047;
            int row = rem >> 5;
            int c = rem & 31;
            int gm = m0 + row;
            uint32_t v = 0u;
            if (gm < n) v = (mat ? sl : sh)[(size_t)gm * 32 + c];
            ((uint32_t*)A_s[mat])[row * (AP / 2) + c] = v;
        }
    }
    __syncthreads();

    int rs = w >> 1;          // row strip (32 rows)
    int cs = w & 1;           // col strip (32 cols)
    int r0 = m0 + rs * 32;

    wmma::fragment<wmma::accumulator, 16, 16, 16, float> acc[2][2];
#pragma unroll
    for (int i = 0; i < 2; i++)
#pragma unroll
        for (int j = 0; j < 2; j++) wmma::fill_fragment(acc[i][j], 0.0f);

#pragma unroll
    for (int kt = 0; kt < 4; kt++) {
        wmma::fragment<wmma::matrix_a, 16, 16, 16, __nv_bfloat16, wmma::row_major> ah[2], al[2];
#pragma unroll
        for (int i = 0; i < 2; i++) {
            wmma::load_matrix_sync(ah[i], &A_s[0][(rs * 32 + i * 16) * AP + kt * 16], AP);
            wmma::load_matrix_sync(al[i], &A_s[1][(rs * 32 + i * 16) * AP + kt * 16], AP);
        }
#pragma unroll
        for (int ct = 0; ct < 2; ct++) {
            int col = cs * 32 + ct * 16;
            wmma::fragment<wmma::matrix_b, 16, 16, 16, __nv_bfloat16, wmma::row_major> bh, bl;
            wmma::load_matrix_sync(bh, &Wh_s[(kt * 16) * WP + col], WP);
            wmma::load_matrix_sync(bl, &Wl_s[(kt * 16) * WP + col], WP);
#pragma unroll
            for (int i = 0; i < 2; i++) {
                wmma::mma_sync(acc[i][ct], ah[i], bh, acc[i][ct]);
                wmma::mma_sync(acc[i][ct], ah[i], bl, acc[i][ct]);
                wmma::mma_sync(acc[i][ct], al[i], bh, acc[i][ct]);
            }
        }
    }

    float* scratch = C_s + w * 256;
    if (blockIdx.y == 0) {
        // y_l -> fp16 (half2 writes), via per-warp scratch
#pragma unroll
        for (int i = 0; i < 2; i++) {
            int gr = r0 + i * 16;
            if (gr >= n) continue;
#pragma unroll
            for (int ct = 0; ct < 2; ct++) {
                wmma::store_matrix_sync(scratch, acc[i][ct], 16, wmma::mem_row_major);
                __syncwarp();
                int colh = cs * 16 + ct * 8;   // half2 column base within 32-half2 row
#pragma unroll
                for (int j = 0; j < 4; j++) {
                    int idx = lane + j * 32;   // 0..127
                    int row = idx >> 3;
                    int c2 = idx & 7;
                    int gm = gr + row;
                    if (gm < n) {
                        float2 f = make_float2(scratch[row * 16 + c2 * 2],
                                               scratch[row * 16 + c2 * 2 + 1]);
                        ((half2*)g_ylh)[(size_t)gm * 32 + colh + c2] = __float22half2_rn(f);
                    }
                }
                __syncwarp();
            }
        }
    } else {
        // y_r fp32
#pragma unroll
        for (int i = 0; i < 2; i++) {
            int gr = r0 + i * 16;
            if (gr + 16 <= n) {
#pragma unroll
                for (int ct = 0; ct < 2; ct++) {
                    int col = cs * 32 + ct * 16;
                    wmma::store_matrix_sync(g_yr + (size_t)gr * 64 + col, acc[i][ct], 64,
                                            wmma::mem_row_major);
                }
            } else if (gr < n) {
#pragma unroll
                for (int ct = 0; ct < 2; ct++) {
                    int col = cs * 32 + ct * 16;
                    wmma::store_matrix_sync(scratch, acc[i][ct], 16, wmma::mem_row_major);
                    __syncwarp();
#pragma unroll
                    for (int j = 0; j < 8; j++) {
                        int idx = lane * 8 + j;
                        int row = idx >> 4;
                        int cc = idx & 15;
                        int gm = gr + row;
                        if (gm < n) g_yr[(size_t)gm * 64 + col + cc] = scratch[idx];
                    }
                    __syncwarp();
                }
            }
        }
    }
}

// ---------------- aggregation + epilogue: warp per node, half2 gather lanes ----------------
// lane owns cols {2*lane, 2*lane+1}. val = mean-gather(g_ylh) + g_yr[own] + bias.
// L=0: relu + bf16 hi/lo split; L=1: fp32 out.
template <int L>
__global__ void __launch_bounds__(256)
aggf_k(const float* __restrict__ bias, float* __restrict__ outp, int n) {
    int w = (blockIdx.x * 256 + threadIdx.x) >> 5;
    int lane = threadIdx.x & 31;
    if (w >= n) return;
    int beg = g_rowptr[w], end = g_rowptr[w + 1];
    float a0 = 0.f, a1 = 0.f;
    const half2* __restrict__ yl2 = (const half2*)g_ylh;
    int p = beg;
    for (; p + 3 < end; p += 4) {
        int s0 = g_csr[p], s1 = g_csr[p + 1], s2 = g_csr[p + 2], s3 = g_csr[p + 3];
        float2 v0 = __half22float2(yl2[(size_t)s0 * 32 + lane]);
        float2 v1 = __half22float2(yl2[(size_t)s1 * 32 + lane]);
        float2 v2 = __half22float2(yl2[(size_t)s2 * 32 + lane]);
        float2 v3 = __half22float2(yl2[(size_t)s3 * 32 + lane]);
        a0 += (v0.x + v1.x) + (v2.x + v3.x);
        a1 += (v0.y + v1.y) + (v2.y + v3.y);
    }
    for (; p < end; p++) {
        float2 v = __half22float2(yl2[(size_t)g_csr[p] * 32 + lane]);
        a0 += v.x;
        a1 += v.y;
    }
    int deg = end - beg;
    float inv = (deg > 0) ? (1.f / (float)deg) : 0.f;
    float2 yr = ((const float2*)(g_yr + (size_t)w * 64))[lane];
    float2 bb = ((const float2*)bias)[lane];
    float v0 = fmaf(a0, inv, yr.x + bb.x);
    float v1 = fmaf(a1, inv, yr.y + bb.y);
    if (L == 0) {
        v0 = fmaxf(v0, 0.f);
        v1 = fmaxf(v1, 0.f);
        __nv_bfloat16 h0 = __float2bfloat16(v0);
        __nv_bfloat16 h1 = __float2bfloat16(v1);
        ((__nv_bfloat162*)(g_hh + (size_t)w * 64))[lane] = __nv_bfloat162(h0, h1);
        ((__nv_bfloat162*)(g_hl + (size_t)w * 64))[lane] =
            __nv_bfloat162(__float2bfloat16(v0 - __bfloat162float(h0)),
                           __float2bfloat16(v1 - __bfloat162float(h1)));
    } else {
        ((float2*)(outp + (size_t)w * 64))[lane] = make_float2(v0, v1);
    }
}

// ---------------- launcher ----------------
extern "C" void kernel_launch(void* const* d_in, const int* in_sizes, int n_in,
                              void* d_out, int out_size) {
    const float* x   = (const float*)d_in[0];
    const int*   ei  = (const int*)d_in[1];   // int32 (JAX x64 disabled)
    const float* W1l = (const float*)d_in[2];
    const float* b1  = (const float*)d_in[3];
    const float* W1r = (const float*)d_in[4];
    const float* W2l = (const float*)d_in[5];
    const float* b2  = (const float*)d_in[6];
    const float* W2r = (const float*)d_in[7];
    float* out = (float*)d_out;

    int n = in_sizes[0] / 64;
    int e = in_sizes[1] / 2;
    if (n > N_MAX) n = N_MAX;
    if (e > E_MAX) e = E_MAX;

    const int* src = ei;
    const int* dst = ei + e;
    int nb = (n + 1023) / 1024;
    dim3 gg((n + 63) / 64, 2);
    int ga = (n + 7) / 8;

    // Launch order keeps gemm_k<0> at slot 4 for ncu (-s 5 -c 1) capture.
    wsplit_k<<<64, 256>>>(W1l, W1r, W2l, W2r);                 // 1
    zero_k<<<(n + 255) / 256, 256>>>(n);                       // 2
    count_k<<<(e + 255) / 256, 256>>>(dst, e, n);              // 3
    gemm_k<0><<<gg, 128>>>(x, n);                              // 4  <- profiled
    scan1_k<<<nb, 256>>>(n);                                   // 5
    scan23_k<<<nb, 256>>>(n, e);                               // 6
    fill_k<<<(e + 255) / 256, 256>>>(src, dst, e, n);          // 7

    // Layer 1 epilogue: h = relu(mean-gather(yl) + yr + b1) -> bf16 split
    aggf_k<0><<<ga, 256>>>(b1, nullptr, n);                    // 8
    // Layer 2
    gemm_k<1><<<gg, 128>>>(x, n);                              // 9
    aggf_k<1><<<ga, 256>>>(b2, out, n);                        // 10
}

// round 15
// speedup vs baseline: 1.1659x; 1.0265x over previous
#include <cuda_runtime.h>
#include <cuda_bf16.h>
#include <cuda_fp16.h>
#include <mma.h>
#include <cstdint>

using namespace nvcuda;

#define N_MAX 100000
#define E_MAX 1000000
#define NB_MAX 128            // ceil(N_MAX/1024) = 98

// ---------------- device scratch (static; device-side references only) ----------------
__device__ int g_cnt[N_MAX];
__device__ int g_rowptr[N_MAX + 1];
__device__ int g_cursor[N_MAX];
__device__ int g_csr[E_MAX];
__device__ int g_bsum[NB_MAX];
__device__ __align__(16) __nv_bfloat16 g_hh[(size_t)N_MAX * 64];
__device__ __align__(16) __nv_bfloat16 g_hl[(size_t)N_MAX * 64];
__device__ __align__(16) __half g_ylh[(size_t)N_MAX * 64];  // lin_l projection, fp16 (gathered)
__device__ float g_yr[(size_t)N_MAX * 64];                  // lin_r projection (root), fp32
// W' = [W_l;W_r] TRANSPOSED: [64 k][128 n] row-major, bf16 hi/lo
__device__ __align__(16) __nv_bfloat16 g_wth[2][8192];
__device__ __align__(16) __nv_bfloat16 g_wtl[2][8192];

// ---------------- CSR build ----------------
__global__ void zero_k(int n) {
    int i = blockIdx.x * blockDim.x + threadIdx.x;
    if (i < n) g_cnt[i] = 0;
}

__global__ void count_k(const int* __restrict__ dst, int e, int n) {
    int i = blockIdx.x * blockDim.x + threadIdx.x;
    if (i < e) {
        int d = dst[i];
        if ((unsigned)d < (unsigned)n) atomicAdd(&g_cnt[d], 1);
    }
}

__global__ void scan1_k(int n) {
    int base = blockIdx.x * 1024;
    int t = threadIdx.x;
    int i0 = base + t * 4;
    int s = 0;
#pragma unroll
    for (int j = 0; j < 4; j++) {
        int i = i0 + j;
        if (i < n) s += g_cnt[i];
    }
#pragma unroll
    for (int o = 16; o; o >>= 1) s += __shfl_down_sync(0xffffffffu, s, o);
    __shared__ int ws[8];
    if ((t & 31) == 0) ws[t >> 5] = s;
    __syncthreads();
    if (t == 0) {
        int tot = 0;
#pragma unroll
        for (int j = 0; j < 8; j++) tot += ws[j];
        g_bsum[blockIdx.x] = tot;
    }
}

// merged scan2+scan3: each block derives its exclusive base from g_bsum itself
__global__ void scan23_k(int n, int e) {
    int t = threadIdx.x;
    int bid = blockIdx.x;
    int val = (t < bid) ? g_bsum[t] : 0;   // bid <= 97 < 256
#pragma unroll
    for (int o = 16; o; o >>= 1) val += __shfl_down_sync(0xffffffffu, val, o);
    __shared__ int wsb[8];
    __shared__ int s_base;
    if ((t & 31) == 0) wsb[t >> 5] = val;
    __syncthreads();
    if (t == 0) {
        int b = 0;
#pragma unroll
        for (int j = 0; j < 8; j++) b += wsb[j];
        s_base = b;
        if (bid == 0) g_rowptr[n] = e;
    }
    __syncthreads();
    int base = s_base;

    int lane = t & 31, wid = t >> 5;
    int i0 = bid * 1024 + t * 4;
    int v[4];
    int tsum = 0;
#pragma unroll
    for (int j = 0; j < 4; j++) {
        v[j] = (i0 + j < n) ? g_cnt[i0 + j] : 0;
        tsum += v[j];
    }
    int incl = tsum;
#pragma unroll
    for (int o = 1; o < 32; o <<= 1) {
        int u = __shfl_up_sync(0xffffffffu, incl, o);
        if (lane >= o) incl += u;
    }
    __shared__ int ws[8];
    if (lane == 31) ws[wid] = incl;
    __syncthreads();
    if (t < 8) {
        int u = ws[t];
        int inc = u;
#pragma unroll
        for (int o = 1; o < 8; o <<= 1) {
            int q = __shfl_up_sync(0xffu, inc, o);
            if (t >= o) inc += q;
        }
        ws[t] = inc - u;
    }
    __syncthreads();
    int excl = incl - tsum + ws[wid] + base;
#pragma unroll
    for (int j = 0; j < 4; j++) {
        int i = i0 + j;
        if (i < n) {
            g_rowptr[i] = excl;
            g_cursor[i] = excl;
            excl += v[j];
        }
    }
}

__global__ void fill_k(const int* __restrict__ src, const int* __restrict__ dst, int e, int n) {
    int i = blockIdx.x * blockDim.x + threadIdx.x;
    if (i < e) {
        int d = dst[i];
        int s = src[i];
        if ((unsigned)d < (unsigned)n && (unsigned)s < (unsigned)n) {
            int pos = atomicAdd(&g_cursor[d], 1);
            g_csr[pos] = s;
        }
    }
}

// ---------------- W' = [W_l ; W_r] -> TRANSPOSED [64 k][128 n] bf16 hi/lo ----------------
__global__ void wsplit_k(const float* __restrict__ W1l, const float* __restrict__ W1r,
                         const float* __restrict__ W2l, const float* __restrict__ W2r) {
    int id = blockIdx.x * blockDim.x + threadIdx.x;
    if (id >= 16384) return;
    int l = id >> 13;
    int rem = id & 8191;
    int nr = rem >> 6;    // 0..127 output row of W'
    int k = rem & 63;     // 0..63 input col
    const float* Wl = l ? W2l : W1l;
    const float* Wr = l ? W2r : W1r;
    float w = (nr < 64) ? Wl[nr * 64 + k] : Wr[(nr - 64) * 64 + k];
    __nv_bfloat16 hi = __float2bfloat16(w);
    __nv_bfloat16 lo = __float2bfloat16(w - __bfloat162float(hi));
    g_wth[l][k * 128 + nr] = hi;     // transposed store
    g_wtl[l][k * 128 + nr] = lo;
}

// ---------------- WMMA GEMM: y[m0:m0+64][c0:c0+64] = A(hi,lo) @ W'(hi,lo)^T ----------------
// 3-term compensated bf16: Ah*Wh + Ah*Wl + Al*Wh, fp32 accumulation.
// Grid (ceil(n/64), 2): blockIdx.y = column half (0 -> y_l fp16, 1 -> y_r fp32).
// 128 threads = 4 warps; warp w: rows [m0+(w>>1)*32, +32) x cols [c0+(w&1)*32, +32); acc[2][2].
// Pitches 72 bf16 (144B = 9 x 16B, so 16B-aligned rows; ldmatrix conflict-free).
// All staging is 16B-vectorized (LDG.128 / STS.128).
#define AP 72
#define WP 72

template <int L>
__global__ void __launch_bounds__(128, 4)
gemm_k(const float* __restrict__ x, int n) {
    __shared__ __nv_bfloat16 A_s[2][64 * AP];
    __shared__ __nv_bfloat16 Wh_s[64 * WP];
    __shared__ __nv_bfloat16 Wl_s[64 * WP];
    __shared__ float C_s[4 * 256];   // per-warp 16x16 epilogue scratch

    int tid = threadIdx.x;
    int w = tid >> 5;
    int lane = tid & 31;
    int m0 = blockIdx.x * 64;
    int c0 = blockIdx.y * 64;

    // stage W tile: 64 k-rows x 64 cols (hi+lo), 8 uint4 per row each
    {
        const __nv_bfloat16* __restrict__ sh = g_wth[L];
        const __nv_bfloat16* __restrict__ sl = g_wtl[L];
#pragma unroll
        for (int i = 0; i < 8; i++) {
            int idx = tid + i * 128;           // 0..1023
            int mat = idx >> 9;                // 0 hi, 1 lo
            int rem = idx & 511;
            int r = rem >> 3;                  // 0..63
            int q4 = rem & 7;                  // 16B chunk
            uint4 v = ((const uint4*)((mat ? sl : sh) + r * 128 + c0))[q4];
            *(uint4*)((mat ? Wl_s : Wh_s) + r * WP + q4 * 8) = v;
        }
    }

    // stage A tile (64 rows x 64 k), hi/lo split, 16B-vectorized
    if (L == 0) {
        // read fp32 x as float4 pairs, split in-register, store uint4 hi + uint4 lo
#pragma unroll
        for (int i = 0; i < 4; i++) {
            int idx = tid + i * 128;           // 0..511
            int row = idx >> 3;                // 0..63
            int c8 = idx & 7;                  // 8-element k chunk
            int gm = m0 + row;
            float4 a = make_float4(0.f, 0.f, 0.f, 0.f);
            float4 b = make_float4(0.f, 0.f, 0.f, 0.f);
            if (gm < n) {
                const float4* p = (const float4*)(x + (size_t)gm * 64 + c8 * 8);
                a = p[0];
                b = p[1];
            }
            float v[8] = {a.x, a.y, a.z, a.w, b.x, b.y, b.z, b.w};
            __nv_bfloat16 hi[8], lo[8];
#pragma unroll
            for (int j = 0; j < 8; j++) {
                hi[j] = __float2bfloat16(v[j]);
                lo[j] = __float2bfloat16(v[j] - __bfloat162float(hi[j]));
            }
            *(uint4*)(&A_s[0][row * AP + c8 * 8]) = *(const uint4*)hi;
            *(uint4*)(&A_s[1][row * AP + c8 * 8]) = *(const uint4*)lo;
        }
    } else {
        const __nv_bfloat16* __restrict__ sh = g_hh;
        const __nv_bfloat16* __restrict__ sl = g_hl;
#pragma unroll
        for (int i = 0; i < 8; i++) {
            int idx = tid + i * 128;           // 0..1023
            int mat = idx >> 9;
            int rem = idx & 511;
            int row = rem >> 3;
            int c8 = rem & 7;
            int gm = m0 + row;
            uint4 v = make_uint4(0u, 0u, 0u, 0u);
            if (gm < n) v = ((const uint4*)((mat ? sl : sh) + (size_t)gm * 64))[c8];
            *(uint4*)(&A_s[mat][row * AP + c8 * 8]) = v;
        }
    }
    __syncthreads();

    int rs = w >> 1;          // row strip (32 rows)
    int cs = w & 1;           // col strip (32 cols)
    int r0 = m0 + rs * 32;

    wmma::fragment<wmma::accumulator, 16, 16, 16, float> acc[2][2];
#pragma unroll
    for (int i = 0; i < 2; i++)
#pragma unroll
        for (int j = 0; j < 2; j++) wmma::fill_fragment(acc[i][j], 0.0f);

#pragma unroll
    for (int kt = 0; kt < 4; kt++) {
        wmma::fragment<wmma::matrix_a, 16, 16, 16, __nv_bfloat16, wmma::row_major> ah[2], al[2];
#pragma unroll
        for (int i = 0; i < 2; i++) {
            wmma::load_matrix_sync(ah[i], &A_s[0][(rs * 32 + i * 16) * AP + kt * 16], AP);
            wmma::load_matrix_sync(al[i], &A_s[1][(rs * 32 + i * 16) * AP + kt * 16], AP);
        }
#pragma unroll
        for (int ct = 0; ct < 2; ct++) {
            int col = cs * 32 + ct * 16;
            wmma::fragment<wmma::matrix_b, 16, 16, 16, __nv_bfloat16, wmma::row_major> bh, bl;
            wmma::load_matrix_sync(bh, &Wh_s[(kt * 16) * WP + col], WP);
            wmma::load_matrix_sync(bl, &Wl_s[(kt * 16) * WP + col], WP);
#pragma unroll
            for (int i = 0; i < 2; i++) {
                wmma::mma_sync(acc[i][ct], ah[i], bh, acc[i][ct]);
                wmma::mma_sync(acc[i][ct], ah[i], bl, acc[i][ct]);
                wmma::mma_sync(acc[i][ct], al[i], bh, acc[i][ct]);
            }
        }
    }

    float* scratch = C_s + w * 256;
    if (blockIdx.y == 0) {
        // y_l -> fp16 (half2 writes), via per-warp scratch
#pragma unroll
        for (int i = 0; i < 2; i++) {
            int gr = r0 + i * 16;
            if (gr >= n) continue;
#pragma unroll
            for (int ct = 0; ct < 2; ct++) {
                wmma::store_matrix_sync(scratch, acc[i][ct], 16, wmma::mem_row_major);
                __syncwarp();
                int colh = cs * 16 + ct * 8;   // half2 column base within 32-half2 row
#pragma unroll
                for (int j = 0; j < 4; j++) {
                    int idx = lane + j * 32;   // 0..127
                    int row = idx >> 3;
                    int c2 = idx & 7;
                    int gm = gr + row;
                    if (gm < n) {
                        float2 f = make_float2(scratch[row * 16 + c2 * 2],
                                               scratch[row * 16 + c2 * 2 + 1]);
                        ((half2*)g_ylh)[(size_t)gm * 32 + colh + c2] = __float22half2_rn(f);
                    }
                }
                __syncwarp();
            }
        }
    } else {
        // y_r fp32
#pragma unroll
        for (int i = 0; i < 2; i++) {
            int gr = r0 + i * 16;
            if (gr + 16 <= n) {
#pragma unroll
                for (int ct = 0; ct < 2; ct++) {
                    int col = cs * 32 + ct * 16;
                    wmma::store_matrix_sync(g_yr + (size_t)gr * 64 + col, acc[i][ct], 64,
                                            wmma::mem_row_major);
                }
            } else if (gr < n) {
#pragma unroll
                for (int ct = 0; ct < 2; ct++) {
                    int col = cs * 32 + ct * 16;
                    wmma::store_matrix_sync(scratch, acc[i][ct], 16, wmma::mem_row_major);
                    __syncwarp();
#pragma unroll
                    for (int j = 0; j < 8; j++) {
                        int idx = lane * 8 + j;
                        int row = idx >> 4;
                        int cc = idx & 15;
                        int gm = gr + row;
                        if (gm < n) g_yr[(size_t)gm * 64 + col + cc] = scratch[idx];
                    }
                    __syncwarp();
                }
            }
        }
    }
}

// ---------------- aggregation + epilogue: warp per node, half2 gather lanes ----------------
// lane owns cols {2*lane, 2*lane+1}. val = mean-gather(g_ylh) + g_yr[own] + bias.
// L=0: relu + bf16 hi/lo split; L=1: fp32 out.
template <int L>
__global__ void __launch_bounds__(256)
aggf_k(const float* __restrict__ bias, float* __restrict__ outp, int n) {
    int w = (blockIdx.x * 256 + threadIdx.x) >> 5;
    int lane = threadIdx.x & 31;
    if (w >= n) return;
    int beg = g_rowptr[w], end = g_rowptr[w + 1];
    float a0 = 0.f, a1 = 0.f;
    const half2* __restrict__ yl2 = (const half2*)g_ylh;
    int p = beg;
    for (; p + 3 < end; p += 4) {
        int s0 = g_csr[p], s1 = g_csr[p + 1], s2 = g_csr[p + 2], s3 = g_csr[p + 3];
        float2 v0 = __half22float2(yl2[(size_t)s0 * 32 + lane]);
        float2 v1 = __half22float2(yl2[(size_t)s1 * 32 + lane]);
        float2 v2 = __half22float2(yl2[(size_t)s2 * 32 + lane]);
        float2 v3 = __half22float2(yl2[(size_t)s3 * 32 + lane]);
        a0 += (v0.x + v1.x) + (v2.x + v3.x);
        a1 += (v0.y + v1.y) + (v2.y + v3.y);
    }
    for (; p < end; p++) {
        float2 v = __half22float2(yl2[(size_t)g_csr[p] * 32 + lane]);
        a0 += v.x;
        a1 += v.y;
    }
    int deg = end - beg;
    float inv = (deg > 0) ? (1.f / (float)deg) : 0.f;
    float2 yr = ((const float2*)(g_yr + (size_t)w * 64))[lane];
    float2 bb = ((const float2*)bias)[lane];
    float v0 = fmaf(a0, inv, yr.x + bb.x);
    float v1 = fmaf(a1, inv, yr.y + bb.y);
    if (L == 0) {
        v0 = fmaxf(v0, 0.f);
        v1 = fmaxf(v1, 0.f);
        __nv_bfloat16 h0 = __float2bfloat16(v0);
        __nv_bfloat16 h1 = __float2bfloat16(v1);
        ((__nv_bfloat162*)(g_hh + (size_t)w * 64))[lane] = __nv_bfloat162(h0, h1);
        ((__nv_bfloat162*)(g_hl + (size_t)w * 64))[lane] =
            __nv_bfloat162(__float2bfloat16(v0 - __bfloat162float(h0)),
                           __float2bfloat16(v1 - __bfloat162float(h1)));
    } else {
        ((float2*)(outp + (size_t)w * 64))[lane] = make_float2(v0, v1);
    }
}

// ---------------- launcher ----------------
extern "C" void kernel_launch(void* const* d_in, const int* in_sizes, int n_in,
                              void* d_out, int out_size) {
    const float* x   = (const float*)d_in[0];
    const int*   ei  = (const int*)d_in[1];   // int32 (JAX x64 disabled)
    const float* W1l = (const float*)d_in[2];
    const float* b1  = (const float*)d_in[3];
    const float* W1r = (const float*)d_in[4];
    const float* W2l = (const float*)d_in[5];
    const float* b2  = (const float*)d_in[6];
    const float* W2r = (const float*)d_in[7];
    float* out = (float*)d_out;

    int n = in_sizes[0] / 64;
    int e = in_sizes[1] / 2;
    if (n > N_MAX) n = N_MAX;
    if (e > E_MAX) e = E_MAX;

    const int* src = ei;
    const int* dst = ei + e;
    int nb = (n + 1023) / 1024;
    dim3 gg((n + 63) / 64, 2);
    int ga = (n + 7) / 8;

    // Launch order keeps gemm_k<0> at slot 4 for ncu (-s 5 -c 1) capture.
    wsplit_k<<<64, 256>>>(W1l, W1r, W2l, W2r);                 // 1
    zero_k<<<(n + 255) / 256, 256>>>(n);                       // 2
    count_k<<<(e + 255) / 256, 256>>>(dst, e, n);              // 3
    gemm_k<0><<<gg, 128>>>(x, n);                              // 4  <- profiled
    scan1_k<<<nb, 256>>>(n);                                   // 5
    scan23_k<<<nb, 256>>>(n, e);                               // 6
    fill_k<<<(e + 255) / 256, 256>>>(src, dst, e, n);          // 7

    // Layer 1 epilogue: h = relu(mean-gather(yl) + yr + b1) -> bf16 split
    aggf_k<0><<<ga, 256>>>(b1, nullptr, n);                    // 8
    // Layer 2
    gemm_k<1><<<gg, 128>>>(x, n);                              // 9
    aggf_k<1><<<ga, 256>>>(b2, out, n);                        // 10
}